// round 8
// baseline (speedup 1.0000x reference)
#include <cuda_runtime.h>
#include <math.h>

// MaskedNorm: B=8, T=4096, C=1024 fp32. Fused persistent kernel:
//  Phase A: masked-row partial sums + unmasked-row copy to out
//  Phase B: fold partials -> per-channel scale/shift (blocks 0..31)
//  Phase C: normalize masked rows
// Grid = 296 blocks @ 1024 thr, 2 blocks/SM on 148 SMs -> exactly one wave,
// so the software grid barrier cannot deadlock.

#define CCH   1024
#define C4    (CCH / 4)      // 256 float4 per row
#define RTOT  32768          // B*T
#define R4TOT (RTOT / 4)     // 8192 row-quads
#define NBLK  296
#define EPSF  1e-4f

__device__ __align__(16) float g_psum[NBLK][CCH];
__device__ __align__(16) float g_psq [NBLK][CCH];
__device__ int      g_pcnt[NBLK];
__device__ __align__(16) float g_scale[CCH];
__device__ __align__(16) float g_shift[CCH];
__device__ unsigned g_bar_cnt[2];   // zero-init; self-resetting
__device__ unsigned g_bar_gen[2];   // monotonic across launches (replay-safe)

__device__ __forceinline__ void grid_barrier(int b) {
    __syncthreads();
    if (threadIdx.x == 0) {
        __threadfence();
        volatile unsigned* genp = &g_bar_gen[b];
        const unsigned g0 = *genp;
        const unsigned my = atomicAdd(&g_bar_cnt[b], 1u);
        if (my == NBLK - 1) {
            g_bar_cnt[b] = 0;
            __threadfence();
            atomicAdd(&g_bar_gen[b], 1u);
        } else {
            while (*genp == g0) { __nanosleep(64); }
        }
        __threadfence();
    }
    __syncthreads();
}

__device__ __forceinline__ void acc4(float4& s, float4& q, const float4 v) {
    s.x += v.x; s.y += v.y; s.z += v.z; s.w += v.w;
    q.x = fmaf(v.x, v.x, q.x);
    q.y = fmaf(v.y, v.y, q.y);
    q.z = fmaf(v.z, v.z, q.z);
    q.w = fmaf(v.w, v.w, q.w);
}

__device__ __forceinline__ float4 nrm4(const float4 v, const float4 sc, const float4 sh) {
    float4 o;
    o.x = fmaf(v.x, sc.x, sh.x); o.y = fmaf(v.y, sc.y, sh.y);
    o.z = fmaf(v.z, sc.z, sh.z); o.w = fmaf(v.w, sc.w, sh.w);
    return o;
}

__global__ __launch_bounds__(1024, 2)
void mn_fused(const float4* __restrict__ y4, const int4* __restrict__ mask4,
              const float* __restrict__ gamma, const float* __restrict__ beta,
              float4* __restrict__ out4) {
    __shared__ float4 ssum[4][256];
    __shared__ float4 ssq [4][256];
    __shared__ int    scnt[4];
    __shared__ int    sn;

    const int t = threadIdx.x & 255;   // channel slot: channels [4t, 4t+4)
    const int g = threadIdx.x >> 8;    // row group 0..3
    const int p = blockIdx.x;

    // ================= Phase A: reduce masked + copy unmasked =================
    {
        float4 s = make_float4(0.f, 0.f, 0.f, 0.f);
        float4 q = make_float4(0.f, 0.f, 0.f, 0.f);
        int cnt = 0;

        for (int r4 = p * 4 + g; r4 < R4TOT; r4 += NBLK * 4) {
            const int  r  = r4 * 4;
            const int4 mk = __ldg(&mask4[r4]);
            // Unconditional loads: both paths need y (stats or copy).
            const float4 v0 = __ldg(&y4[(r + 0) * C4 + t]);
            const float4 v1 = __ldg(&y4[(r + 1) * C4 + t]);
            const float4 v2 = __ldg(&y4[(r + 2) * C4 + t]);
            const float4 v3 = __ldg(&y4[(r + 3) * C4 + t]);
            if (mk.x > 0) { acc4(s, q, v0); cnt++; } else __stcs(&out4[(r + 0) * C4 + t], v0);
            if (mk.y > 0) { acc4(s, q, v1); cnt++; } else __stcs(&out4[(r + 1) * C4 + t], v1);
            if (mk.z > 0) { acc4(s, q, v2); cnt++; } else __stcs(&out4[(r + 2) * C4 + t], v2);
            if (mk.w > 0) { acc4(s, q, v3); cnt++; } else __stcs(&out4[(r + 3) * C4 + t], v3);
        }
        ssum[g][t] = s;
        ssq [g][t] = q;
        if (t == 0) scnt[g] = cnt;   // identical across t within a group
        __syncthreads();

        if (g == 0) {
            float4 S = ssum[0][t], Q = ssq[0][t];
            #pragma unroll
            for (int i = 1; i < 4; i++) {
                const float4 a = ssum[i][t], b = ssq[i][t];
                S.x += a.x; S.y += a.y; S.z += a.z; S.w += a.w;
                Q.x += b.x; Q.y += b.y; Q.z += b.z; Q.w += b.w;
            }
            reinterpret_cast<float4*>(g_psum[p])[t] = S;
            reinterpret_cast<float4*>(g_psq [p])[t] = Q;
            if (t == 0) g_pcnt[p] = scnt[0] + scnt[1] + scnt[2] + scnt[3];
        }
    }

    grid_barrier(0);

    // ================= Phase B: fold partials (blocks 0..31) =================
    if (p < 32) {
        float* sb = reinterpret_cast<float*>(ssum);   // [32][32]
        float* sq = reinterpret_cast<float*>(ssq);    // [32][32]
        const int lane = threadIdx.x & 31;
        const int w    = threadIdx.x >> 5;            // 0..31
        const int c    = p * 32 + lane;

        float s = 0.0f, q = 0.0f;
        for (int pp = w; pp < NBLK; pp += 32) {
            s += g_psum[pp][c];
            q += g_psq [pp][c];
        }
        sb[w * 32 + lane] = s;
        sq[w * 32 + lane] = q;

        if (w == 0) {
            int n = 0;
            for (int pp = lane; pp < NBLK; pp += 32) n += g_pcnt[pp];
            #pragma unroll
            for (int o = 16; o; o >>= 1) n += __shfl_down_sync(0xffffffffu, n, o);
            if (lane == 0) sn = n;
        }
        __syncthreads();

        if (w == 0) {
            float S = 0.0f, Q = 0.0f;
            #pragma unroll
            for (int i = 0; i < 32; i++) { S += sb[i * 32 + lane]; Q += sq[i * 32 + lane]; }
            const float nf   = (float)sn;
            const float mean = S / nf;
            const float var  = (Q - S * S / nf) / (nf - 1.0f);
            const float sd   = sqrtf(var);
            const float sc   = __ldg(&gamma[c]) / (sd + EPSF);
            g_scale[c] = sc;
            g_shift[c] = __ldg(&beta[c]) - mean * sc;   // out = fma(y, sc, shift)
        }
    }

    grid_barrier(1);

    // ================= Phase C: normalize masked rows =================
    {
        const float4 sc = reinterpret_cast<const float4*>(g_scale)[t];
        const float4 sh = reinterpret_cast<const float4*>(g_shift)[t];

        for (int r4 = p * 4 + g; r4 < R4TOT; r4 += NBLK * 4) {
            const int  r  = r4 * 4;
            const int4 mk = __ldg(&mask4[r4]);
            if (mk.x > 0) __stcs(&out4[(r + 0) * C4 + t], nrm4(__ldg(&y4[(r + 0) * C4 + t]), sc, sh));
            if (mk.y > 0) __stcs(&out4[(r + 1) * C4 + t], nrm4(__ldg(&y4[(r + 1) * C4 + t]), sc, sh));
            if (mk.z > 0) __stcs(&out4[(r + 2) * C4 + t], nrm4(__ldg(&y4[(r + 2) * C4 + t]), sc, sh));
            if (mk.w > 0) __stcs(&out4[(r + 3) * C4 + t], nrm4(__ldg(&y4[(r + 3) * C4 + t]), sc, sh));
        }
    }
}

extern "C" void kernel_launch(void* const* d_in, const int* in_sizes, int n_in,
                              void* d_out, int out_size) {
    const float* y     = (const float*)d_in[0];
    const int*   mask  = (const int*)  d_in[1];
    const float* gamma = (const float*)d_in[2];
    const float* beta  = (const float*)d_in[3];
    float*       out   = (float*)d_out;

    mn_fused<<<NBLK, 1024>>>((const float4*)y, (const int4*)mask, gamma, beta,
                             (float4*)out);
}

// round 9
// speedup vs baseline: 1.0888x; 1.0888x over previous
#include <cuda_runtime.h>
#include <math.h>

// MaskedNorm: B=8, T=4096, C=1024 fp32.
// k1: dense read; masked rows -> partial sums (L2-retained), unmasked rows -> copy to out (evict)
// k2: fold partials -> per-channel scale/shift
// k3: normalize masked rows only (reads hit L2 from k1)

#define CCH   1024
#define C4    (CCH / 4)      // 256 float4 per row
#define RTOT  32768          // B*T
#define R4TOT (RTOT / 4)     // 8192 row-quads
#define R2TOT (RTOT / 2)     // 16384 row-pairs
#define NBLK  296            // k1 blocks: 2/SM x 148 SMs (1024 thr each)
#define G3    2048           // k3 blocks: 16384/2048 = 8 iters exact
#define EPSF  1e-4f

__device__ __align__(16) float g_psum[NBLK][CCH];
__device__ __align__(16) float g_psq [NBLK][CCH];
__device__ int   g_pcnt[NBLK];
__device__ __align__(16) float g_scale[CCH];
__device__ __align__(16) float g_shift[CCH];

__device__ __forceinline__ void acc4(float4& s, float4& q, const float4 v) {
    s.x += v.x; s.y += v.y; s.z += v.z; s.w += v.w;
    q.x = fmaf(v.x, v.x, q.x);
    q.y = fmaf(v.y, v.y, q.y);
    q.z = fmaf(v.z, v.z, q.z);
    q.w = fmaf(v.w, v.w, q.w);
}

// ---------- k1: masked reduce + unmasked copy (dense streaming) ----------
// 1024 threads = 4 row-groups x 256 channel-threads. Masked rows: __ldg
// (default policy -> retained in L2 for k3). Unmasked rows: __ldcs load +
// __stcs copy (evict-first both ways; they never get touched again).
__global__ __launch_bounds__(1024, 2)
void mn_main(const float4* __restrict__ y4, const int4* __restrict__ mask4,
             float4* __restrict__ out4) {
    __shared__ float4 ssum[4][256];
    __shared__ float4 ssq [4][256];
    __shared__ int    scnt[4];
    const int t = threadIdx.x & 255;   // channel slot (4 channels)
    const int g = threadIdx.x >> 8;    // row group 0..3
    const int p = blockIdx.x;

    float4 s = make_float4(0.f, 0.f, 0.f, 0.f);
    float4 q = make_float4(0.f, 0.f, 0.f, 0.f);
    int cnt = 0;

    for (int r4 = p * 4 + g; r4 < R4TOT; r4 += NBLK * 4) {
        const int  r  = r4 * 4;
        const int4 mk = __ldg(&mask4[r4]);
        if (mk.x > 0) { acc4(s, q, __ldg(&y4[(r + 0) * C4 + t])); cnt++; }
        else          { __stcs(&out4[(r + 0) * C4 + t], __ldcs(&y4[(r + 0) * C4 + t])); }
        if (mk.y > 0) { acc4(s, q, __ldg(&y4[(r + 1) * C4 + t])); cnt++; }
        else          { __stcs(&out4[(r + 1) * C4 + t], __ldcs(&y4[(r + 1) * C4 + t])); }
        if (mk.z > 0) { acc4(s, q, __ldg(&y4[(r + 2) * C4 + t])); cnt++; }
        else          { __stcs(&out4[(r + 2) * C4 + t], __ldcs(&y4[(r + 2) * C4 + t])); }
        if (mk.w > 0) { acc4(s, q, __ldg(&y4[(r + 3) * C4 + t])); cnt++; }
        else          { __stcs(&out4[(r + 3) * C4 + t], __ldcs(&y4[(r + 3) * C4 + t])); }
    }
    ssum[g][t] = s;
    ssq [g][t] = q;
    if (t == 0) scnt[g] = cnt;   // identical across t within a group
    __syncthreads();

    if (g == 0) {
        float4 S = ssum[0][t], Q = ssq[0][t];
        #pragma unroll
        for (int i = 1; i < 4; i++) {
            const float4 a = ssum[i][t], b = ssq[i][t];
            S.x += a.x; S.y += a.y; S.z += a.z; S.w += a.w;
            Q.x += b.x; Q.y += b.y; Q.z += b.z; Q.w += b.w;
        }
        reinterpret_cast<float4*>(g_psum[p])[t] = S;
        reinterpret_cast<float4*>(g_psq [p])[t] = Q;
        if (t == 0) g_pcnt[p] = scnt[0] + scnt[1] + scnt[2] + scnt[3];
    }
}

// ---------- k2: fold partials -> scale/shift (parallel, coalesced) ----------
__global__ __launch_bounds__(256, 8)
void mn_stats(const float* __restrict__ gamma, const float* __restrict__ beta) {
    __shared__ float ssum[8][32];
    __shared__ float ssq [8][32];
    __shared__ int   sn;
    const int lane = threadIdx.x & 31;
    const int w    = threadIdx.x >> 5;
    const int c    = blockIdx.x * 32 + lane;

    float s = 0.0f, q = 0.0f;
    #pragma unroll 4
    for (int p = w; p < NBLK; p += 8) {
        s += g_psum[p][c];
        q += g_psq [p][c];
    }
    ssum[w][lane] = s;
    ssq [w][lane] = q;

    if (w == 0) {
        int n = 0;
        for (int p = lane; p < NBLK; p += 32) n += g_pcnt[p];
        #pragma unroll
        for (int o = 16; o; o >>= 1) n += __shfl_down_sync(0xffffffffu, n, o);
        if (lane == 0) sn = n;
    }
    __syncthreads();

    if (w == 0) {
        float S = 0.0f, Q = 0.0f;
        #pragma unroll
        for (int i = 0; i < 8; i++) { S += ssum[i][lane]; Q += ssq[i][lane]; }
        const float nf   = (float)sn;
        const float mean = S / nf;
        const float var  = (Q - S * S / nf) / (nf - 1.0f);
        const float sd   = sqrtf(var);
        const float sc   = __ldg(&gamma[c]) / (sd + EPSF);
        g_scale[c] = sc;
        g_shift[c] = __ldg(&beta[c]) - mean * sc;   // out = fma(y, sc, shift)
    }
}

// ---------- k3: normalize masked rows only (L2-hit reads) ----------
// 2 rows/iter (low MLP_p1 -> under cross-CTA L1tex-queue threshold).
__global__ __launch_bounds__(256, 8)
void mn_norm(const float4* __restrict__ y4, const int* __restrict__ mask,
             float4* __restrict__ out4) {
    const int t = threadIdx.x;
    const float4 sc = reinterpret_cast<const float4*>(g_scale)[t];
    const float4 sh = reinterpret_cast<const float4*>(g_shift)[t];

    #pragma unroll 1
    for (int r2 = blockIdx.x; r2 < R2TOT; r2 += G3) {
        const int r  = r2 * 2;
        const int m0 = __ldg(&mask[r + 0]);
        const int m1 = __ldg(&mask[r + 1]);
        if (m0 > 0) {
            float4 v = __ldg(&y4[(r + 0) * C4 + t]);
            v.x = fmaf(v.x, sc.x, sh.x); v.y = fmaf(v.y, sc.y, sh.y);
            v.z = fmaf(v.z, sc.z, sh.z); v.w = fmaf(v.w, sc.w, sh.w);
            __stcs(&out4[(r + 0) * C4 + t], v);
        }
        if (m1 > 0) {
            float4 v = __ldg(&y4[(r + 1) * C4 + t]);
            v.x = fmaf(v.x, sc.x, sh.x); v.y = fmaf(v.y, sc.y, sh.y);
            v.z = fmaf(v.z, sc.z, sh.z); v.w = fmaf(v.w, sc.w, sh.w);
            __stcs(&out4[(r + 1) * C4 + t], v);
        }
    }
}

extern "C" void kernel_launch(void* const* d_in, const int* in_sizes, int n_in,
                              void* d_out, int out_size) {
    const float* y     = (const float*)d_in[0];
    const int*   mask  = (const int*)  d_in[1];
    const float* gamma = (const float*)d_in[2];
    const float* beta  = (const float*)d_in[3];
    float*       out   = (float*)d_out;

    mn_main<<<NBLK, 1024>>>((const float4*)y, (const int4*)mask, (float4*)out);
    mn_stats<<<32, 256>>>(gamma, beta);
    mn_norm<<<G3, 256>>>((const float4*)y, mask, (float4*)out);
}